// round 12
// baseline (speedup 1.0000x reference)
#include <cuda_runtime.h>
#include <cstdint>

#define NN 4096
#define FF 128
#define HH 8
#define DD 8
#define HD 64
#define ECAP 72     // CSR row capacity (mean E~41, sigma~6.4; E>ECAP handled by slow fallback)
#define FPAD 68     // s_feats row stride: 68 mod 32 == 4 -> 8 stripes x 4 dims span 32 distinct banks
#define APAD 9      // s_an row stride: stride 9 -> 8 stripes on distinct banks
#define FBLK 256    // number of feats-GEMM blocks at the head of kernel 1's grid

__device__ float g_feats[NN * HD];
__device__ float g_as[NN * HH];
__device__ float g_an[NN * HH];
__device__ int   g_eidx[NN * ECAP];
__device__ int   g_ecnt[NN];

__device__ __forceinline__ void cp_async4(uint32_t dst, const void* src) {
    asm volatile("cp.async.ca.shared.global [%0], [%1], 4;" :: "r"(dst), "l"(src));
}
__device__ __forceinline__ void cp_async16(uint32_t dst, const void* src) {
    asm volatile("cp.async.ca.shared.global [%0], [%1], 16;" :: "r"(dst), "l"(src));
}
__device__ __forceinline__ void cp_async_commit() {
    asm volatile("cp.async.commit_group;");
}
__device__ __forceinline__ void cp_async_wait0() {
    asm volatile("cp.async.wait_group 0;");
}

// ---------------- Kernel 1: heterogeneous — feats GEMM (blocks 0..255) + A-scan CSR (blocks 256..4351) ----
__global__ __launch_bounds__(256) void scan_feats_kernel(const float* __restrict__ A,
                                                         const float* __restrict__ X,
                                                         const float* __restrict__ W,
                                                         const float* __restrict__ att_self,
                                                         const float* __restrict__ att_neigh) {
    __shared__ float Ws[FF][HD];      // 32 KB (feats path); scan path reuses the first bytes
    __shared__ float Xs[16][133];     // feats path; reused as Fs[16][68] in epilogue
    const int tid = threadIdx.x;
    const int lane = tid & 31;
    const int w = tid >> 5;

    if (blockIdx.x < FBLK) {
        // ================= feats = X @ W, fused a_s/a_n epilogue =================
        const int rbase = blockIdx.x * 16;
        {
            const float4* Wv = (const float4*)W;
            float4* Wsv = (float4*)&Ws[0][0];
            #pragma unroll
            for (int k = 0; k < 8; ++k) Wsv[tid + k * 256] = Wv[tid + k * 256];
        }
        {
            #pragma unroll
            for (int k = 0; k < 2; ++k) {
                const int li = tid + k * 256;
                const int r = li >> 5;
                const int c4 = (li & 31) << 2;
                float4 v = *(const float4*)&X[(rbase + r) * FF + c4];
                Xs[r][c4 + 0] = v.x; Xs[r][c4 + 1] = v.y;
                Xs[r][c4 + 2] = v.z; Xs[r][c4 + 3] = v.w;
            }
        }
        __syncthreads();

        const int r = tid & 15;
        const int cg = tid >> 4;
        float4 acc = make_float4(0.f, 0.f, 0.f, 0.f);
        #pragma unroll 16
        for (int k = 0; k < FF; ++k) {
            const float xv = Xs[r][k];
            const float4 wv = *(const float4*)&Ws[k][cg * 4];
            acc.x += xv * wv.x; acc.y += xv * wv.y;
            acc.z += xv * wv.z; acc.w += xv * wv.w;
        }
        *(float4*)&g_feats[(rbase + r) * HD + cg * 4] = acc;

        __syncthreads();
        float* Fs = &Xs[0][0];
        Fs[r * 68 + cg * 4 + 0] = acc.x;
        Fs[r * 68 + cg * 4 + 1] = acc.y;
        Fs[r * 68 + cg * 4 + 2] = acc.z;
        Fs[r * 68 + cg * 4 + 3] = acc.w;
        __syncthreads();
        if (tid < 128) {
            const int rr = tid >> 3;
            const int h = tid & 7;
            float ds = 0.f, dn = 0.f;
            #pragma unroll
            for (int d = 0; d < DD; ++d) {
                const float f = Fs[rr * 68 + h * DD + d];
                ds += f * __ldg(&att_self[h * DD + d]);
                dn += f * __ldg(&att_neigh[h * DD + d]);
            }
            g_as[(rbase + rr) * HH + h] = ds;
            g_an[(rbase + rr) * HH + h] = dn;
        }
    } else {
        // ================= pure streaming A-scan -> CSR =================
        __shared__ int s_wtot[8];
        const int i = blockIdx.x - FBLK;

        // coalesced A-row read: thread owns cols j = 1024*k + 4*tid + q
        const float4* Arow4 = (const float4*)(A + (size_t)i * NN);
        float4 v0 = Arow4[tid];
        float4 v1 = Arow4[256 + tid];
        float4 v2 = Arow4[512 + tid];
        float4 v3 = Arow4[768 + tid];

        // exact bitmask: 4 independent FFMA chains (A is exactly 0.0/1.0)
        float mf0 = fmaf(v0.y, 2.f, v0.x);
        mf0 = fmaf(v0.z, 4.f, mf0);  mf0 = fmaf(v0.w, 8.f, mf0);
        float mf1 = fmaf(v1.y, 2.f, v1.x);
        mf1 = fmaf(v1.z, 4.f, mf1);  mf1 = fmaf(v1.w, 8.f, mf1);
        float mf2 = fmaf(v2.y, 2.f, v2.x);
        mf2 = fmaf(v2.z, 4.f, mf2);  mf2 = fmaf(v2.w, 8.f, mf2);
        float mf3 = fmaf(v3.y, 2.f, v3.x);
        mf3 = fmaf(v3.z, 4.f, mf3);  mf3 = fmaf(v3.w, 8.f, mf3);
        unsigned mask = __float2uint_rn(mf0)
                      | (__float2uint_rn(mf1) << 4)
                      | (__float2uint_rn(mf2) << 8)
                      | (__float2uint_rn(mf3) << 12);
        const int c = __popc(mask);

        // warp scan
        int inc = c;
        #pragma unroll
        for (int off = 1; off < 32; off <<= 1) {
            int y = __shfl_up_sync(0xffffffffu, inc, off);
            if (lane >= off) inc += y;
        }
        if (lane == 31) s_wtot[w] = inc;
        __syncthreads();

        // every warp reconstructs the 8 warp totals
        int raw = (lane < 8) ? s_wtot[lane] : 0;
        int sc = raw;
        #pragma unroll
        for (int o = 1; o < 8; o <<= 1) {
            int y = __shfl_up_sync(0xffffffffu, sc, o);
            if (lane >= o) sc += y;
        }
        const int E = __shfl_sync(0xffffffffu, sc, 7);
        const int woff = __shfl_sync(0xffffffffu, sc, w) - __shfl_sync(0xffffffffu, raw, w);

        if (tid == 0) g_ecnt[i] = E;

        // compact: write column indices (deterministic order); cap at ECAP
        int p = woff + inc - c;
        unsigned m = mask;
        const int base = tid << 2;
        while (m) {
            const int b = __ffs(m) - 1;
            m &= m - 1;
            if (p < ECAP) g_eidx[i * ECAP + p] = ((b >> 2) << 10) | base | (b & 3);
            ++p;
        }
    }
}

// ---------------- Kernel 2: aggregate from CSR ----------------
__global__ __launch_bounds__(256, 8) void gat_agg_kernel(const float* __restrict__ A,
                                                         const float* __restrict__ bias,
                                                         float* __restrict__ out) {
    __shared__ int   s_idx[ECAP];            // 288 B
    __shared__ float s_an[ECAP][APAD];       // 2.6 KB edge-major, stride 9
    __shared__ float s_feats[ECAP][FPAD];    // 19.1 KB staged feats rows
    __shared__ float s_as[HH];

    const int i = blockIdx.x;
    const int tid = threadIdx.x;
    const int w = tid >> 5;
    const int lane = tid & 31;

    const int E = g_ecnt[i];
    if (tid < HH) s_as[tid] = g_as[i * HH + tid];

    if (E <= ECAP) {
        if (tid < E) s_idx[tid] = g_eidx[i * ECAP + tid];
        __syncthreads();

        // async staging: warp per edge; lanes 0-15 stage feats (16B), lanes 16-23 stage a_n (4B)
        {
            const uint32_t sf_base = (uint32_t)__cvta_generic_to_shared(&s_feats[0][0]);
            const uint32_t sa_base = (uint32_t)__cvta_generic_to_shared(&s_an[0][0]);
            for (int e = w; e < E; e += 8) {
                const int j = s_idx[e];
                if (lane < 16)
                    cp_async16(sf_base + (e * FPAD + lane * 4) * 4, g_feats + j * HD + lane * 4);
                else if (lane < 16 + HH)
                    cp_async4(sa_base + (e * APAD + (lane - 16)) * 4, g_an + j * HH + (lane - 16));
            }
            cp_async_commit();
        }
        cp_async_wait0();
        __syncthreads();

        // warp = head; lane = stripe(0..7)*4 + dim(0..3); each lane covers dims d and d+4
        const int h = w;
        const int stripe = lane >> 2;
        const int d = lane & 3;
        const float as_i = s_as[h];
        const int hd = h * DD + d;
        float acc0 = 0.f, acc1 = 0.f, s = 0.f;
        #pragma unroll 2
        for (int e = stripe; e < E; e += 8) {
            float l = as_i + s_an[e][h];
            l = fmaxf(l, 0.2f * l);                // leaky_relu(0.2); logits O(0.1) -> no max-sub
            const float wt = __expf(l);
            s += wt;
            acc0 = fmaf(wt, s_feats[e][hd],     acc0);
            acc1 = fmaf(wt, s_feats[e][hd + 4], acc1);
        }
        #pragma unroll
        for (int o = 4; o <= 16; o <<= 1) {
            acc0 += __shfl_xor_sync(0xffffffffu, acc0, o);
            acc1 += __shfl_xor_sync(0xffffffffu, acc1, o);
            s    += __shfl_xor_sync(0xffffffffu, s, o);
        }

        if (lane < 4) {
            const float inv = __fdividef(1.f, s);
            out[i * HD + h * DD + lane] =
                fmaxf(fmaf(acc0, inv, __ldg(&bias[h * DD + lane])), 0.f);
            out[i * HD + h * DD + lane + 4] =
                fmaxf(fmaf(acc1, inv, __ldg(&bias[h * DD + lane + 4])), 0.f);
        }
    } else {
        // slow fallback (statistically unreachable): re-scan the A row directly
        __syncthreads();
        const int h = w;
        const float as_i = s_as[h];
        const float* Ar = A + (size_t)i * NN;

        float m = -3.0e38f;
        for (int j = lane; j < NN; j += 32) {
            if (Ar[j] > 0.5f) {
                float l = as_i + g_an[j * HH + h];
                l = fmaxf(l, 0.2f * l);
                m = fmaxf(m, l);
            }
        }
        #pragma unroll
        for (int o = 16; o; o >>= 1) m = fmaxf(m, __shfl_xor_sync(0xffffffffu, m, o));

        float s = 0.f;
        float acc[8] = {0.f, 0.f, 0.f, 0.f, 0.f, 0.f, 0.f, 0.f};
        for (int j = lane; j < NN; j += 32) {
            if (Ar[j] > 0.5f) {
                float l = as_i + g_an[j * HH + h];
                l = fmaxf(l, 0.2f * l);
                const float wt = __expf(l - m);
                s += wt;
                const float4* fp = (const float4*)(g_feats + j * HD + h * DD);
                const float4 f0 = fp[0], f1 = fp[1];
                acc[0] += wt * f0.x; acc[1] += wt * f0.y; acc[2] += wt * f0.z; acc[3] += wt * f0.w;
                acc[4] += wt * f1.x; acc[5] += wt * f1.y; acc[6] += wt * f1.z; acc[7] += wt * f1.w;
            }
        }
        #pragma unroll
        for (int o = 16; o; o >>= 1) {
            s += __shfl_xor_sync(0xffffffffu, s, o);
            #pragma unroll
            for (int dd = 0; dd < 8; ++dd) acc[dd] += __shfl_xor_sync(0xffffffffu, acc[dd], o);
        }
        if (lane == 0) {
            const float inv = 1.0f / s;
            #pragma unroll
            for (int dd = 0; dd < 8; ++dd)
                out[i * HD + h * DD + dd] = fmaxf(acc[dd] * inv + bias[h * DD + dd], 0.f);
        }
    }
}

extern "C" void kernel_launch(void* const* d_in, const int* in_sizes, int n_in,
                              void* d_out, int out_size) {
    const float* X         = (const float*)d_in[0];  // [4096,128]
    const float* A         = (const float*)d_in[1];  // [4096,4096]
    const float* W         = (const float*)d_in[2];  // [128,64]
    const float* att_self  = (const float*)d_in[3];  // [1,8,8]
    const float* att_neigh = (const float*)d_in[4];  // [1,8,8]
    const float* bias      = (const float*)d_in[5];  // [1,8,8]
    float* out             = (float*)d_out;          // [4096,64]

    scan_feats_kernel<<<FBLK + NN, 256>>>(A, X, W, att_self, att_neigh);
    gat_agg_kernel<<<NN, 256>>>(A, bias, out);
}

// round 13
// speedup vs baseline: 1.5778x; 1.5778x over previous
#include <cuda_runtime.h>
#include <cstdint>

#define NN 4096
#define FF 128
#define HH 8
#define DD 8
#define HD 64
#define ECAP 72     // fast-path edge cap (mean E~41, sigma~6.4; slow fallback keeps correctness for outliers)
#define FPAD 68     // s_feats row stride: 68 mod 32 == 4 -> 8 stripes x 4 dims span 32 distinct banks
#define APAD 9      // s_an row stride: 9 -> 8 stripes on distinct banks

__device__ float g_feats[NN * HD];
__device__ float g_as[NN * HH];
__device__ float g_an[NN * HH];

__device__ __forceinline__ void cp_async4(uint32_t dst, const void* src) {
    asm volatile("cp.async.ca.shared.global [%0], [%1], 4;" :: "r"(dst), "l"(src));
}
__device__ __forceinline__ void cp_async16(uint32_t dst, const void* src) {
    asm volatile("cp.async.ca.shared.global [%0], [%1], 16;" :: "r"(dst), "l"(src));
}
__device__ __forceinline__ void cp_async_commit() {
    asm volatile("cp.async.commit_group;");
}
__device__ __forceinline__ void cp_async_wait0() {
    asm volatile("cp.async.wait_group 0;");
}

// ---------------- Kernel 1: feats = X @ W  fused with a_s / a_n epilogue ----------------
__global__ __launch_bounds__(256) void feats_att_kernel(const float* __restrict__ X,
                                                        const float* __restrict__ W,
                                                        const float* __restrict__ att_self,
                                                        const float* __restrict__ att_neigh) {
    __shared__ float Ws[FF][HD];      // 32 KB
    __shared__ float Xs[16][133];     // stride 133; reused as Fs[16][68] in epilogue
    const int tid = threadIdx.x;
    const int rbase = blockIdx.x * 16;

    {
        const float4* Wv = (const float4*)W;
        float4* Wsv = (float4*)&Ws[0][0];
        #pragma unroll
        for (int k = 0; k < 8; ++k) Wsv[tid + k * 256] = Wv[tid + k * 256];
    }
    {
        #pragma unroll
        for (int k = 0; k < 2; ++k) {
            const int li = tid + k * 256;
            const int r = li >> 5;
            const int c4 = (li & 31) << 2;
            float4 v = *(const float4*)&X[(rbase + r) * FF + c4];
            Xs[r][c4 + 0] = v.x; Xs[r][c4 + 1] = v.y;
            Xs[r][c4 + 2] = v.z; Xs[r][c4 + 3] = v.w;
        }
    }
    __syncthreads();

    const int r = tid & 15;
    const int cg = tid >> 4;
    float4 acc = make_float4(0.f, 0.f, 0.f, 0.f);
    #pragma unroll 16
    for (int k = 0; k < FF; ++k) {
        const float xv = Xs[r][k];
        const float4 wv = *(const float4*)&Ws[k][cg * 4];
        acc.x += xv * wv.x; acc.y += xv * wv.y;
        acc.z += xv * wv.z; acc.w += xv * wv.w;
    }
    *(float4*)&g_feats[(rbase + r) * HD + cg * 4] = acc;

    __syncthreads();
    float* Fs = &Xs[0][0];
    Fs[r * 68 + cg * 4 + 0] = acc.x;
    Fs[r * 68 + cg * 4 + 1] = acc.y;
    Fs[r * 68 + cg * 4 + 2] = acc.z;
    Fs[r * 68 + cg * 4 + 3] = acc.w;
    __syncthreads();
    if (tid < 128) {
        const int rr = tid >> 3;
        const int h = tid & 7;
        float ds = 0.f, dn = 0.f;
        #pragma unroll
        for (int d = 0; d < DD; ++d) {
            const float f = Fs[rr * 68 + h * DD + d];
            ds += f * __ldg(&att_self[h * DD + d]);
            dn += f * __ldg(&att_neigh[h * DD + d]);
        }
        g_as[(rbase + rr) * HH + h] = ds;
        g_an[(rbase + rr) * HH + h] = dn;
    }
}

// ---------------- Kernel 2: per-row sparse softmax + aggregation (fused scan+agg) ----------------
__global__ __launch_bounds__(256, 8) void gat_main_kernel(const float* __restrict__ A,
                                                          const float* __restrict__ bias,
                                                          float* __restrict__ out) {
    __shared__ int   s_idx[ECAP];            // 288 B
    __shared__ float s_an[ECAP][APAD];       // 2.6 KB edge-major, stride 9
    __shared__ float s_feats[ECAP][FPAD];    // 19.1 KB staged feats rows
    __shared__ int   s_wtot[8];
    __shared__ float s_as[HH];

    const int i = blockIdx.x;
    const int tid = threadIdx.x;
    const int w = tid >> 5;
    const int lane = tid & 31;

    if (tid < HH) s_as[tid] = g_as[i * HH + tid];

    // --- coalesced A-row read: thread owns cols j = 1024*k + 4*tid + q ---
    const float4* Arow4 = (const float4*)(A + (size_t)i * NN);
    float4 v0 = Arow4[tid];
    float4 v1 = Arow4[256 + tid];
    float4 v2 = Arow4[512 + tid];
    float4 v3 = Arow4[768 + tid];

    // --- exact bitmask: 4 independent FFMA chains (A is exactly 0.0/1.0) ---
    float mf0 = fmaf(v0.y, 2.f, v0.x);
    mf0 = fmaf(v0.z, 4.f, mf0);  mf0 = fmaf(v0.w, 8.f, mf0);
    float mf1 = fmaf(v1.y, 2.f, v1.x);
    mf1 = fmaf(v1.z, 4.f, mf1);  mf1 = fmaf(v1.w, 8.f, mf1);
    float mf2 = fmaf(v2.y, 2.f, v2.x);
    mf2 = fmaf(v2.z, 4.f, mf2);  mf2 = fmaf(v2.w, 8.f, mf2);
    float mf3 = fmaf(v3.y, 2.f, v3.x);
    mf3 = fmaf(v3.z, 4.f, mf3);  mf3 = fmaf(v3.w, 8.f, mf3);
    unsigned mask = __float2uint_rn(mf0)
                  | (__float2uint_rn(mf1) << 4)
                  | (__float2uint_rn(mf2) << 8)
                  | (__float2uint_rn(mf3) << 12);
    const int c = __popc(mask);

    // --- warp-level inclusive scan of per-thread counts ---
    int inc = c;
    #pragma unroll
    for (int off = 1; off < 32; off <<= 1) {
        int y = __shfl_up_sync(0xffffffffu, inc, off);
        if (lane >= off) inc += y;
    }
    if (lane == 31) s_wtot[w] = inc;
    __syncthreads();

    // --- every warp reconstructs all 8 warp totals (single barrier total for the scan) ---
    int raw = (lane < 8) ? s_wtot[lane] : 0;
    int sc = raw;
    #pragma unroll
    for (int o = 1; o < 8; o <<= 1) {
        int y = __shfl_up_sync(0xffffffffu, sc, o);
        if (lane >= o) sc += y;
    }
    const int E = __shfl_sync(0xffffffffu, sc, 7);
    const int woff = __shfl_sync(0xffffffffu, sc, w) - __shfl_sync(0xffffffffu, raw, w);

    if (E <= ECAP) {
        // --- ffs-based compaction: work proportional to hits ---
        {
            int p = woff + inc - c;
            unsigned m = mask;
            const int base = tid << 2;
            while (m) {
                const int b = __ffs(m) - 1;
                m &= m - 1;
                s_idx[p++] = ((b >> 2) << 10) | base | (b & 3);
            }
        }
        __syncthreads();

        // --- uniform async staging (no lane divergence) ---
        {
            const uint32_t sf_base = (uint32_t)__cvta_generic_to_shared(&s_feats[0][0]);
            const uint32_t sa_base = (uint32_t)__cvta_generic_to_shared(&s_an[0][0]);
            // feats: 2 edges per warp-iteration; all 32 lanes issue cp16
            const int half = lane >> 4;          // 0: edge e, 1: edge e+1
            const int l16 = lane & 15;
            for (int e = 2 * w + half; e < E; e += 16) {
                const int j = s_idx[e];
                cp_async16(sf_base + (e * FPAD + l16 * 4) * 4, g_feats + j * HD + l16 * 4);
            }
            // a_n: flat tid-mapped cp4 over E*8 values
            for (int t = tid; t < E * HH; t += 256) {
                const int e = t >> 3;
                const int hh = t & 7;
                cp_async4(sa_base + (e * APAD + hh) * 4, g_an + s_idx[e] * HH + hh);
            }
            cp_async_commit();
        }
        cp_async_wait0();
        __syncthreads();

        // --- warp = head; lane = stripe(0..7)*4 + dim(0..3); dims d and d+4 per lane ---
        const int h = w;
        const int stripe = lane >> 2;
        const int d = lane & 3;
        const float as_i = s_as[h];
        const int hd = h * DD + d;
        float acc0 = 0.f, acc1 = 0.f, s = 0.f;
        #pragma unroll 2
        for (int e = stripe; e < E; e += 8) {
            float l = as_i + s_an[e][h];           // 8 distinct banks (APAD=9), 4-lane bcast
            l = fmaxf(l, 0.2f * l);                // leaky_relu(0.2); logits O(0.1) -> no max-sub
            const float wt = __expf(l);
            s += wt;
            acc0 = fmaf(wt, s_feats[e][hd],     acc0);   // conflict-free (FPAD=68)
            acc1 = fmaf(wt, s_feats[e][hd + 4], acc1);
        }
        #pragma unroll
        for (int o = 4; o <= 16; o <<= 1) {
            acc0 += __shfl_xor_sync(0xffffffffu, acc0, o);
            acc1 += __shfl_xor_sync(0xffffffffu, acc1, o);
            s    += __shfl_xor_sync(0xffffffffu, s, o);
        }

        if (lane < 4) {
            const float inv = __fdividef(1.f, s);
            out[i * HD + h * DD + lane] =
                fmaxf(fmaf(acc0, inv, __ldg(&bias[h * DD + lane])), 0.f);
            out[i * HD + h * DD + lane + 4] =
                fmaxf(fmaf(acc1, inv, __ldg(&bias[h * DD + lane + 4])), 0.f);
        }
    } else {
        // --- slow fallback (statistically unreachable, correctness-preserving) ---
        __syncthreads();
        const int h = w;
        const float as_i = s_as[h];
        const float* Ar = A + (size_t)i * NN;

        float m = -3.0e38f;
        for (int j = lane; j < NN; j += 32) {
            if (Ar[j] > 0.5f) {
                float l = as_i + g_an[j * HH + h];
                l = fmaxf(l, 0.2f * l);
                m = fmaxf(m, l);
            }
        }
        #pragma unroll
        for (int o = 16; o; o >>= 1) m = fmaxf(m, __shfl_xor_sync(0xffffffffu, m, o));

        float s = 0.f;
        float acc[8] = {0.f, 0.f, 0.f, 0.f, 0.f, 0.f, 0.f, 0.f};
        for (int j = lane; j < NN; j += 32) {
            if (Ar[j] > 0.5f) {
                float l = as_i + g_an[j * HH + h];
                l = fmaxf(l, 0.2f * l);
                const float wt = __expf(l - m);
                s += wt;
                const float4* fp = (const float4*)(g_feats + j * HD + h * DD);
                const float4 f0 = fp[0], f1 = fp[1];
                acc[0] += wt * f0.x; acc[1] += wt * f0.y; acc[2] += wt * f0.z; acc[3] += wt * f0.w;
                acc[4] += wt * f1.x; acc[5] += wt * f1.y; acc[6] += wt * f1.z; acc[7] += wt * f1.w;
            }
        }
        #pragma unroll
        for (int o = 16; o; o >>= 1) {
            s += __shfl_xor_sync(0xffffffffu, s, o);
            #pragma unroll
            for (int dd = 0; dd < 8; ++dd) acc[dd] += __shfl_xor_sync(0xffffffffu, acc[dd], o);
        }
        if (lane == 0) {
            const float inv = 1.0f / s;
            #pragma unroll
            for (int dd = 0; dd < 8; ++dd)
                out[i * HD + h * DD + dd] = fmaxf(acc[dd] * inv + bias[h * DD + dd], 0.f);
        }
    }
}

extern "C" void kernel_launch(void* const* d_in, const int* in_sizes, int n_in,
                              void* d_out, int out_size) {
    const float* X         = (const float*)d_in[0];  // [4096,128]
    const float* A         = (const float*)d_in[1];  // [4096,4096]
    const float* W         = (const float*)d_in[2];  // [128,64]
    const float* att_self  = (const float*)d_in[3];  // [1,8,8]
    const float* att_neigh = (const float*)d_in[4];  // [1,8,8]
    const float* bias      = (const float*)d_in[5];  // [1,8,8]
    float* out             = (float*)d_out;          // [4096,64]

    feats_att_kernel<<<NN / 16, 256>>>(X, W, att_self, att_neigh);
    gat_main_kernel<<<NN, 256>>>(A, bias, out);
}

// round 14
// speedup vs baseline: 1.6945x; 1.0740x over previous
#include <cuda_runtime.h>
#include <cstdint>

#define NN 4096
#define FF 128
#define HH 8
#define DD 8
#define HD 64
#define ECAP 72     // per-row edge cap (mean E~41, sigma~6.4; warp-local slow fallback keeps correctness)
#define LG2E 1.44269504088896340736f

__device__ float g_feats[NN * HD];
__device__ float g_as[NN * HH];   // pre-scaled by log2(e)
__device__ float g_an[NN * HH];   // pre-scaled by log2(e)

// ---------------- Kernel 1: feats = X @ W  fused with (log2e-scaled) a_s / a_n epilogue ----------------
__global__ __launch_bounds__(256) void feats_att_kernel(const float* __restrict__ X,
                                                        const float* __restrict__ W,
                                                        const float* __restrict__ att_self,
                                                        const float* __restrict__ att_neigh) {
    __shared__ float Ws[FF][HD];      // 32 KB
    __shared__ float Xs[16][133];     // stride 133; reused as Fs[16][68] in epilogue
    const int tid = threadIdx.x;
    const int rbase = blockIdx.x * 16;

    {
        const float4* Wv = (const float4*)W;
        float4* Wsv = (float4*)&Ws[0][0];
        #pragma unroll
        for (int k = 0; k < 8; ++k) Wsv[tid + k * 256] = Wv[tid + k * 256];
    }
    {
        #pragma unroll
        for (int k = 0; k < 2; ++k) {
            const int li = tid + k * 256;
            const int r = li >> 5;
            const int c4 = (li & 31) << 2;
            float4 v = *(const float4*)&X[(rbase + r) * FF + c4];
            Xs[r][c4 + 0] = v.x; Xs[r][c4 + 1] = v.y;
            Xs[r][c4 + 2] = v.z; Xs[r][c4 + 3] = v.w;
        }
    }
    __syncthreads();

    const int r = tid & 15;
    const int cg = tid >> 4;
    float4 acc = make_float4(0.f, 0.f, 0.f, 0.f);
    #pragma unroll 16
    for (int k = 0; k < FF; ++k) {
        const float xv = Xs[r][k];
        const float4 wv = *(const float4*)&Ws[k][cg * 4];
        acc.x += xv * wv.x; acc.y += xv * wv.y;
        acc.z += xv * wv.z; acc.w += xv * wv.w;
    }
    *(float4*)&g_feats[(rbase + r) * HD + cg * 4] = acc;

    __syncthreads();
    float* Fs = &Xs[0][0];
    Fs[r * 68 + cg * 4 + 0] = acc.x;
    Fs[r * 68 + cg * 4 + 1] = acc.y;
    Fs[r * 68 + cg * 4 + 2] = acc.z;
    Fs[r * 68 + cg * 4 + 3] = acc.w;
    __syncthreads();
    if (tid < 128) {
        const int rr = tid >> 3;
        const int h = tid & 7;
        float ds = 0.f, dn = 0.f;
        #pragma unroll
        for (int d = 0; d < DD; ++d) {
            const float f = Fs[rr * 68 + h * DD + d];
            ds += f * __ldg(&att_self[h * DD + d]);
            dn += f * __ldg(&att_neigh[h * DD + d]);
        }
        g_as[(rbase + rr) * HH + h] = ds * LG2E;   // pre-scale: exp(x) = exp2(LG2E*x)
        g_an[(rbase + rr) * HH + h] = dn * LG2E;   // lrelu commutes with positive scaling
    }
}

// ---------------- Kernel 2: warp-per-row sparse softmax + aggregation ----------------
// warp w of block b owns row i = b*8+w. lane = h*4+q: head h (0..7), dim-pair q (0..3).
// No block barriers, no cross-warp communication, no reductions.
__global__ __launch_bounds__(256) void gat_row_kernel(const float* __restrict__ A,
                                                      const float* __restrict__ bias,
                                                      float* __restrict__ out) {
    __shared__ int s_idx[8][ECAP];   // 2.3 KB, warp-private segments

    const int w = threadIdx.x >> 5;
    const int lane = threadIdx.x & 31;
    const int i = blockIdx.x * 8 + w;
    const int h = lane >> 2;

    // --- A-row scan: 32 coalesced LDG.128 per warp; exact 16-bit FFMA masks ---
    const float4* Arow4 = (const float4*)(A + (size_t)i * NN);
    unsigned mw[8];
    #pragma unroll
    for (int g = 0; g < 8; ++g) {
        float mf = 0.f;
        #pragma unroll
        for (int k4 = 0; k4 < 4; ++k4) {
            // col = (g*4+k4)*128 + lane*4 + {0..3}; bit = k4*4 + {0..3}
            const float4 v = Arow4[(g * 4 + k4) * 32 + lane];
            mf = fmaf(v.x, (float)(1u << (k4 * 4 + 0)), mf);
            mf = fmaf(v.y, (float)(1u << (k4 * 4 + 1)), mf);
            mf = fmaf(v.z, (float)(1u << (k4 * 4 + 2)), mf);
            mf = fmaf(v.w, (float)(1u << (k4 * 4 + 3)), mf);
        }
        mw[g] = __float2uint_rn(mf);   // exact: sum of distinct 2^b, b<16, < 2^24
    }
    int c = 0;
    #pragma unroll
    for (int g = 0; g < 8; ++g) c += __popc(mw[g]);

    // warp-level inclusive scan of per-lane counts
    int inc = c;
    #pragma unroll
    for (int off = 1; off < 32; off <<= 1) {
        int y = __shfl_up_sync(0xffffffffu, inc, off);
        if (lane >= off) inc += y;
    }
    const int E = __shfl_sync(0xffffffffu, inc, 31);

    const float as_i = __ldg(&g_as[i * HH + h]);

    if (E <= ECAP) {
        // --- ffs compaction into the warp's s_idx segment (deterministic order) ---
        int p = inc - c;
        #pragma unroll
        for (int g = 0; g < 8; ++g) {
            unsigned m = mw[g];
            const int cbase = g * 512 + lane * 4;
            while (m) {
                const int b = __ffs(m) - 1;
                m &= m - 1;
                s_idx[w][p++] = cbase + ((b >> 2) << 7) + (b & 3);
            }
        }
        __syncwarp();

        // --- agg: per edge, 32 lanes consume the whole 256B feats row (1 LDG.64/lane) ---
        float acc0 = 0.f, acc1 = 0.f, s = 0.f;
        const float* fbase = g_feats + lane * 2;    // lane*2 == h*8 + q*2
        #pragma unroll 4
        for (int e = 0; e < E; ++e) {
            const int j = s_idx[w][e];              // warp-uniform broadcast
            float l = as_i + __ldg(&g_an[j * HH + h]);   // 8 addrs, 4-lane bcast, 1 sector
            l = fmaxf(l, 0.2f * l);                 // leaky_relu(0.2); logits O(0.1) -> no max-sub
            const float wt = exp2f(l);              // pre-scaled -> bare MUFU.EX2
            s += wt;                                // replicated within q-group (free)
            const float2 f = *(const float2*)(fbase + j * HD);
            acc0 = fmaf(wt, f.x, acc0);
            acc1 = fmaf(wt, f.y, acc1);
        }

        // --- epilogue: no reductions; each lane owns dims (lane*2, lane*2+1) ---
        const float inv = __fdividef(1.f, s);
        const float2 b2 = *(const float2*)(bias + lane * 2);
        float2 o;
        o.x = fmaxf(fmaf(acc0, inv, b2.x), 0.f);
        o.y = fmaxf(fmaf(acc1, inv, b2.y), 0.f);
        *(float2*)(out + i * HD + lane * 2) = o;    // 256B coalesced per warp
    } else {
        // --- slow fallback (statistically unreachable): direct full-row pass, same math ---
        float acc0 = 0.f, acc1 = 0.f, s = 0.f;
        const float* Ar = A + (size_t)i * NN;
        const float* fbase = g_feats + lane * 2;
        for (int j = 0; j < NN; ++j) {
            if (__ldg(&Ar[j]) > 0.5f) {
                float l = as_i + __ldg(&g_an[j * HH + h]);
                l = fmaxf(l, 0.2f * l);
                const float wt = exp2f(l);
                s += wt;
                const float2 f = *(const float2*)(fbase + j * HD);
                acc0 = fmaf(wt, f.x, acc0);
                acc1 = fmaf(wt, f.y, acc1);
            }
        }
        const float inv = __fdividef(1.f, s);
        const float2 b2 = *(const float2*)(bias + lane * 2);
        float2 o;
        o.x = fmaxf(fmaf(acc0, inv, b2.x), 0.f);
        o.y = fmaxf(fmaf(acc1, inv, b2.y), 0.f);
        *(float2*)(out + i * HD + lane * 2) = o;
    }
}

extern "C" void kernel_launch(void* const* d_in, const int* in_sizes, int n_in,
                              void* d_out, int out_size) {
    const float* X         = (const float*)d_in[0];  // [4096,128]
    const float* A         = (const float*)d_in[1];  // [4096,4096]
    const float* W         = (const float*)d_in[2];  // [128,64]
    const float* att_self  = (const float*)d_in[3];  // [1,8,8]
    const float* att_neigh = (const float*)d_in[4];  // [1,8,8]
    const float* bias      = (const float*)d_in[5];  // [1,8,8]
    float* out             = (float*)d_out;          // [4096,64]

    feats_att_kernel<<<NN / 16, 256>>>(X, W, att_self, att_neigh);
    gat_row_kernel<<<NN / 8, 256>>>(A, bias, out);
}

// round 16
// speedup vs baseline: 1.7015x; 1.0041x over previous
#include <cuda_runtime.h>
#include <cstdint>

#define NN 4096
#define FF 128
#define HH 8
#define DD 8
#define HD 64
#define ECAPH 64    // per-half-row edge cap (mean ~20.5, sigma ~4.5; warp-local fallback keeps correctness)
#define LG2E 1.44269504088896340736f

__device__ float g_feats[NN * HD];
__device__ float g_as[NN * HH];   // pre-scaled by log2(e)
__device__ float g_an[NN * HH];   // pre-scaled by log2(e)

// ---------------- Kernel 1: feats = X @ W  fused with (log2e-scaled) a_s / a_n epilogue ----------------
__global__ __launch_bounds__(256) void feats_att_kernel(const float* __restrict__ X,
                                                        const float* __restrict__ W,
                                                        const float* __restrict__ att_self,
                                                        const float* __restrict__ att_neigh) {
    __shared__ float Ws[FF][HD];      // 32 KB
    __shared__ float Xs[16][133];     // stride 133; reused as Fs[16][68] in epilogue
    const int tid = threadIdx.x;
    const int rbase = blockIdx.x * 16;

    {
        const float4* Wv = (const float4*)W;
        float4* Wsv = (float4*)&Ws[0][0];
        #pragma unroll
        for (int k = 0; k < 8; ++k) Wsv[tid + k * 256] = Wv[tid + k * 256];
    }
    {
        #pragma unroll
        for (int k = 0; k < 2; ++k) {
            const int li = tid + k * 256;
            const int r = li >> 5;
            const int c4 = (li & 31) << 2;
            float4 v = *(const float4*)&X[(rbase + r) * FF + c4];
            Xs[r][c4 + 0] = v.x; Xs[r][c4 + 1] = v.y;
            Xs[r][c4 + 2] = v.z; Xs[r][c4 + 3] = v.w;
        }
    }
    __syncthreads();

    const int r = tid & 15;
    const int cg = tid >> 4;
    float4 acc = make_float4(0.f, 0.f, 0.f, 0.f);
    #pragma unroll 16
    for (int k = 0; k < FF; ++k) {
        const float xv = Xs[r][k];
        const float4 wv = *(const float4*)&Ws[k][cg * 4];
        acc.x += xv * wv.x; acc.y += xv * wv.y;
        acc.z += xv * wv.z; acc.w += xv * wv.w;
    }
    *(float4*)&g_feats[(rbase + r) * HD + cg * 4] = acc;

    __syncthreads();
    float* Fs = &Xs[0][0];
    Fs[r * 68 + cg * 4 + 0] = acc.x;
    Fs[r * 68 + cg * 4 + 1] = acc.y;
    Fs[r * 68 + cg * 4 + 2] = acc.z;
    Fs[r * 68 + cg * 4 + 3] = acc.w;
    __syncthreads();
    if (tid < 128) {
        const int rr = tid >> 3;
        const int h = tid & 7;
        float ds = 0.f, dn = 0.f;
        #pragma unroll
        for (int d = 0; d < DD; ++d) {
            const float f = Fs[rr * 68 + h * DD + d];
            ds += f * __ldg(&att_self[h * DD + d]);
            dn += f * __ldg(&att_neigh[h * DD + d]);
        }
        g_as[(rbase + rr) * HH + h] = ds * LG2E;   // exp(x) = exp2(LG2E*x)
        g_an[(rbase + rr) * HH + h] = dn * LG2E;   // lrelu commutes with positive scaling
    }
}

// ---------------- Kernel 2: warp-pair-per-row sparse softmax + aggregation ----------------
// Block = 8 warps = 4 rows. Warps (2t, 2t+1) own row i = blockIdx.x*4 + t; warp parity ph
// scans/aggregates A-row half [ph*2048, ph*2048+2048). Partial sums combine via smem
// (exp without max-subtraction is additive). lane = h*4+q owns output dims lane*2, lane*2+1.
__global__ __launch_bounds__(256) void gat_row_kernel(const float* __restrict__ A,
                                                      const float* __restrict__ bias,
                                                      float* __restrict__ out) {
    __shared__ int   s_idx[8][ECAPH];     // 2 KB, warp-private segments
    __shared__ float s_red[4][32][3];     // 1.5 KB; lane stride 3 (gcd(3,32)=1 -> conflict-free)

    const int w = threadIdx.x >> 5;
    const int lane = threadIdx.x & 31;
    const int t = w >> 1;
    const int ph = w & 1;
    const int i = blockIdx.x * 4 + t;
    const int h = lane >> 2;

    // --- scan this warp's half: 16 coalesced LDG.128; exact 16-bit FFMA masks ---
    const float4* Arow4 = (const float4*)(A + (size_t)i * NN) + ph * 512;
    unsigned mw[4];
    #pragma unroll
    for (int g = 0; g < 4; ++g) {
        float mf = 0.f;
        #pragma unroll
        for (int k4 = 0; k4 < 4; ++k4) {
            const float4 v = Arow4[(g * 4 + k4) * 32 + lane];
            mf = fmaf(v.x, (float)(1u << (k4 * 4 + 0)), mf);
            mf = fmaf(v.y, (float)(1u << (k4 * 4 + 1)), mf);
            mf = fmaf(v.z, (float)(1u << (k4 * 4 + 2)), mf);
            mf = fmaf(v.w, (float)(1u << (k4 * 4 + 3)), mf);
        }
        mw[g] = __float2uint_rn(mf);   // exact: sum of distinct 2^b, b<16
    }
    int c = __popc(mw[0]) + __popc(mw[1]) + __popc(mw[2]) + __popc(mw[3]);

    // warp-level inclusive scan of per-lane counts
    int inc = c;
    #pragma unroll
    for (int off = 1; off < 32; off <<= 1) {
        int y = __shfl_up_sync(0xffffffffu, inc, off);
        if (lane >= off) inc += y;
    }
    const int E = __shfl_sync(0xffffffffu, inc, 31);   // edges in this half

    const float as_i = __ldg(&g_as[i * HH + h]);
    float acc0 = 0.f, acc1 = 0.f, s = 0.f;
    const float* fbase = g_feats + lane * 2;           // lane*2 == h*8 + q*2

    if (E <= ECAPH) {
        // --- ffs compaction into the warp's segment (deterministic order) ---
        int p = inc - c;
        #pragma unroll
        for (int g = 0; g < 4; ++g) {
            unsigned m = mw[g];
            const int cbase = ph * 2048 + g * 512 + lane * 4;
            while (m) {
                const int b = __ffs(m) - 1;
                m &= m - 1;
                s_idx[w][p++] = cbase + ((b >> 2) << 7) + (b & 3);
            }
        }
        __syncwarp();

        // --- agg over this half's edges: whole 256B feats row per edge (1 LDG.64/lane) ---
        #pragma unroll 4
        for (int e = 0; e < E; ++e) {
            const int j = s_idx[w][e];                 // warp-uniform broadcast
            float l = as_i + __ldg(&g_an[j * HH + h]); // 8 addrs, 4-lane bcast, 1 sector
            l = fmaxf(l, 0.2f * l);                    // leaky_relu(0.2); logits O(0.1)
            const float wt = exp2f(l);
            s += wt;
            const float2 f = *(const float2*)(fbase + j * HD);
            acc0 = fmaf(wt, f.x, acc0);
            acc1 = fmaf(wt, f.y, acc1);
        }
    } else {
        // --- fallback (statistically unreachable): direct pass over this half ---
        const float* Ar = A + (size_t)i * NN + ph * 2048;
        for (int j = 0; j < 2048; ++j) {
            if (__ldg(&Ar[j]) > 0.5f) {
                const int jj = ph * 2048 + j;
                float l = as_i + __ldg(&g_an[jj * HH + h]);
                l = fmaxf(l, 0.2f * l);
                const float wt = exp2f(l);
                s += wt;
                const float2 f = *(const float2*)(fbase + jj * HD);
                acc0 = fmaf(wt, f.x, acc0);
                acc1 = fmaf(wt, f.y, acc1);
            }
        }
    }

    // --- combine the warp pair: odd warp publishes, even warp finishes ---
    if (ph == 1) {
        s_red[t][lane][0] = acc0;
        s_red[t][lane][1] = acc1;
        s_red[t][lane][2] = s;
    }
    __syncthreads();
    if (ph == 0) {
        acc0 += s_red[t][lane][0];
        acc1 += s_red[t][lane][1];
        s    += s_red[t][lane][2];
        const float inv = __fdividef(1.f, s);
        const float2 b2 = *(const float2*)(bias + lane * 2);
        float2 o;
        o.x = fmaxf(fmaf(acc0, inv, b2.x), 0.f);
        o.y = fmaxf(fmaf(acc1, inv, b2.y), 0.f);
        *(float2*)(out + i * HD + lane * 2) = o;       // 256B coalesced per warp
    }
}

extern "C" void kernel_launch(void* const* d_in, const int* in_sizes, int n_in,
                              void* d_out, int out_size) {
    const float* X         = (const float*)d_in[0];  // [4096,128]
    const float* A         = (const float*)d_in[1];  // [4096,4096]
    const float* W         = (const float*)d_in[2];  // [128,64]
    const float* att_self  = (const float*)d_in[3];  // [1,8,8]
    const float* att_neigh = (const float*)d_in[4];  // [1,8,8]
    const float* bias      = (const float*)d_in[5];  // [1,8,8]
    float* out             = (float*)d_out;          // [4096,64]

    feats_att_kernel<<<NN / 16, 256>>>(X, W, att_self, att_neigh);
    gat_row_kernel<<<NN / 4, 256>>>(A, bias, out);
}

// round 17
// speedup vs baseline: 1.8885x; 1.1099x over previous
#include <cuda_runtime.h>
#include <cstdint>

#define NN 4096
#define FF 128
#define HH 8
#define DD 8
#define HD 64
#define ECAPH 64    // per-half-row edge cap (mean ~20.5, sigma ~4.5; warp-local fallback keeps correctness)
#define LG2E 1.44269504088896340736f

__device__ float g_feats[NN * HD];
__device__ float g_as[NN * HH];   // pre-scaled by log2(e)
__device__ float g_an[NN * HH];   // pre-scaled by log2(e)

__device__ __forceinline__ float ex2_approx(float x) {
    float r;
    asm("ex2.approx.ftz.f32 %0, %1;" : "=f"(r) : "f"(x));
    return r;
}

// ---------------- Kernel 1: feats = X @ W  fused with (log2e-scaled) a_s / a_n epilogue ----------------
__global__ __launch_bounds__(256) void feats_att_kernel(const float* __restrict__ X,
                                                        const float* __restrict__ W,
                                                        const float* __restrict__ att_self,
                                                        const float* __restrict__ att_neigh) {
    __shared__ float Ws[FF][HD];      // 32 KB
    __shared__ float Xs[16][133];     // stride 133; reused as Fs[16][68] in epilogue
    const int tid = threadIdx.x;
    const int rbase = blockIdx.x * 16;

    {
        const float4* Wv = (const float4*)W;
        float4* Wsv = (float4*)&Ws[0][0];
        #pragma unroll
        for (int k = 0; k < 8; ++k) Wsv[tid + k * 256] = Wv[tid + k * 256];
    }
    {
        #pragma unroll
        for (int k = 0; k < 2; ++k) {
            const int li = tid + k * 256;
            const int r = li >> 5;
            const int c4 = (li & 31) << 2;
            float4 v = *(const float4*)&X[(rbase + r) * FF + c4];
            Xs[r][c4 + 0] = v.x; Xs[r][c4 + 1] = v.y;
            Xs[r][c4 + 2] = v.z; Xs[r][c4 + 3] = v.w;
        }
    }
    __syncthreads();

    const int r = tid & 15;
    const int cg = tid >> 4;
    float4 acc = make_float4(0.f, 0.f, 0.f, 0.f);
    #pragma unroll 16
    for (int k = 0; k < FF; ++k) {
        const float xv = Xs[r][k];
        const float4 wv = *(const float4*)&Ws[k][cg * 4];
        acc.x += xv * wv.x; acc.y += xv * wv.y;
        acc.z += xv * wv.z; acc.w += xv * wv.w;
    }
    *(float4*)&g_feats[(rbase + r) * HD + cg * 4] = acc;

    __syncthreads();
    float* Fs = &Xs[0][0];
    Fs[r * 68 + cg * 4 + 0] = acc.x;
    Fs[r * 68 + cg * 4 + 1] = acc.y;
    Fs[r * 68 + cg * 4 + 2] = acc.z;
    Fs[r * 68 + cg * 4 + 3] = acc.w;
    __syncthreads();
    if (tid < 128) {
        const int rr = tid >> 3;
        const int h = tid & 7;
        float ds = 0.f, dn = 0.f;
        #pragma unroll
        for (int d = 0; d < DD; ++d) {
            const float f = Fs[rr * 68 + h * DD + d];
            ds += f * __ldg(&att_self[h * DD + d]);
            dn += f * __ldg(&att_neigh[h * DD + d]);
        }
        g_as[(rbase + rr) * HH + h] = ds * LG2E;   // exp(x) = exp2(LG2E*x)
        g_an[(rbase + rr) * HH + h] = dn * LG2E;   // lrelu commutes with positive scaling
    }
}

// ---------------- Kernel 2: warp-pair-per-row sparse softmax + aggregation ----------------
// Warps (2t, 2t+1) own row i = blockIdx.x*4 + t; parity ph scans half [ph*2048, +2048).
// Partials combine via smem (exp without max-subtraction is additive).
// lane = h*4+q owns output dims lane*2, lane*2+1.  64-reg budget for load batching.
__global__ __launch_bounds__(256, 4) void gat_row_kernel(const float* __restrict__ A,
                                                         const float* __restrict__ bias,
                                                         float* __restrict__ out) {
    __shared__ int   s_idx[8][ECAPH];     // 2 KB, warp-private segments (rows 256B-aligned)
    __shared__ float s_red[4][32][3];     // 1.5 KB; lane stride 3 -> conflict-free

    const int w = threadIdx.x >> 5;
    const int lane = threadIdx.x & 31;
    const int t = w >> 1;
    const int ph = w & 1;
    const int i = blockIdx.x * 4 + t;
    const int h = lane >> 2;

    // --- scan this warp's half: 16 coalesced LDG.128; exact per-nibble FFMA masks ---
    const float4* Arow4 = (const float4*)(A + (size_t)i * NN) + ph * 512;
    unsigned mw[4];
    #pragma unroll
    for (int g = 0; g < 4; ++g) {
        unsigned m = 0;
        #pragma unroll
        for (int k4 = 0; k4 < 4; ++k4) {
            const float4 v = Arow4[(g * 4 + k4) * 32 + lane];
            float mf = fmaf(v.y, 2.f, v.x);     // 4-deep chain per nibble (ILP across k4)
            mf = fmaf(v.z, 4.f, mf);
            mf = fmaf(v.w, 8.f, mf);
            m |= __float2uint_rn(mf) << (k4 * 4);   // exact: nibble <= 15
        }
        mw[g] = m;
    }
    int c = __popc(mw[0]) + __popc(mw[1]) + __popc(mw[2]) + __popc(mw[3]);

    // warp-level inclusive scan of per-lane counts
    int inc = c;
    #pragma unroll
    for (int off = 1; off < 32; off <<= 1) {
        int y = __shfl_up_sync(0xffffffffu, inc, off);
        if (lane >= off) inc += y;
    }
    const int E = __shfl_sync(0xffffffffu, inc, 31);   // edges in this half

    const float as_i = __ldg(&g_as[i * HH + h]);
    float acc0 = 0.f, acc1 = 0.f, s = 0.f;
    const float* fbase = g_feats + lane * 2;           // lane*2 == h*8 + q*2

    if (E <= ECAPH) {
        // --- ffs compaction into the warp's segment (deterministic order) ---
        int p = inc - c;
        #pragma unroll
        for (int g = 0; g < 4; ++g) {
            unsigned m = mw[g];
            const int cbase = ph * 2048 + g * 512 + lane * 4;
            while (m) {
                const int b = __ffs(m) - 1;
                m &= m - 1;
                s_idx[w][p++] = cbase + ((b >> 2) << 7) + (b & 3);
            }
        }
        __syncwarp();

        // --- pipelined quad aggregation: LDS.128 indices -> 8 batched LDGs -> compute ---
        const int E4 = E & ~3;
        #pragma unroll 2
        for (int e0 = 0; e0 < E4; e0 += 4) {
            const int4 jj = *(const int4*)&s_idx[w][e0];
            const float a0 = __ldg(&g_an[jj.x * HH + h]);
            const float a1 = __ldg(&g_an[jj.y * HH + h]);
            const float a2 = __ldg(&g_an[jj.z * HH + h]);
            const float a3 = __ldg(&g_an[jj.w * HH + h]);
            const float2 f0 = *(const float2*)(fbase + jj.x * HD);
            const float2 f1 = *(const float2*)(fbase + jj.y * HD);
            const float2 f2 = *(const float2*)(fbase + jj.z * HD);
            const float2 f3 = *(const float2*)(fbase + jj.w * HD);
            float l0 = as_i + a0; l0 = fmaxf(l0, 0.2f * l0);
            float l1 = as_i + a1; l1 = fmaxf(l1, 0.2f * l1);
            float l2 = as_i + a2; l2 = fmaxf(l2, 0.2f * l2);
            float l3 = as_i + a3; l3 = fmaxf(l3, 0.2f * l3);
            const float w0 = ex2_approx(l0);
            const float w1 = ex2_approx(l1);
            const float w2 = ex2_approx(l2);
            const float w3 = ex2_approx(l3);
            s += w0 + w1 + w2 + w3;
            acc0 = fmaf(w0, f0.x, acc0); acc1 = fmaf(w0, f0.y, acc1);
            acc0 = fmaf(w1, f1.x, acc0); acc1 = fmaf(w1, f1.y, acc1);
            acc0 = fmaf(w2, f2.x, acc0); acc1 = fmaf(w2, f2.y, acc1);
            acc0 = fmaf(w3, f3.x, acc0); acc1 = fmaf(w3, f3.y, acc1);
        }
        for (int e = E4; e < E; ++e) {                 // remainder (0-3)
            const int j = s_idx[w][e];
            float l = as_i + __ldg(&g_an[j * HH + h]);
            l = fmaxf(l, 0.2f * l);
            const float wt = ex2_approx(l);
            s += wt;
            const float2 f = *(const float2*)(fbase + j * HD);
            acc0 = fmaf(wt, f.x, acc0);
            acc1 = fmaf(wt, f.y, acc1);
        }
    } else {
        // --- fallback (statistically unreachable): direct pass over this half ---
        const float* Ar = A + (size_t)i * NN + ph * 2048;
        for (int j = 0; j < 2048; ++j) {
            if (__ldg(&Ar[j]) > 0.5f) {
                const int jj = ph * 2048 + j;
                float l = as_i + __ldg(&g_an[jj * HH + h]);
                l = fmaxf(l, 0.2f * l);
                const float wt = ex2_approx(l);
                s += wt;
                const float2 f = *(const float2*)(fbase + jj * HD);
                acc0 = fmaf(wt, f.x, acc0);
                acc1 = fmaf(wt, f.y, acc1);
            }
        }
    }

    // --- combine the warp pair: odd warp publishes, even warp finishes ---
    if (ph == 1) {
        s_red[t][lane][0] = acc0;
        s_red[t][lane][1] = acc1;
        s_red[t][lane][2] = s;
    }
    __syncthreads();
    if (ph == 0) {
        acc0 += s_red[t][lane][0];
        acc1 += s_red[t][lane][1];
        s    += s_red[t][lane][2];
        const float inv = __fdividef(1.f, s);
        const float2 b2 = *(const float2*)(bias + lane * 2);
        float2 o;
        o.x = fmaxf(fmaf(acc0, inv, b2.x), 0.f);
        o.y = fmaxf(fmaf(acc1, inv, b2.y), 0.f);
        *(float2*)(out + i * HD + lane * 2) = o;       // 256B coalesced per warp
    }
}

extern "C" void kernel_launch(void* const* d_in, const int* in_sizes, int n_in,
                              void* d_out, int out_size) {
    const float* X         = (const float*)d_in[0];  // [4096,128]
    const float* A         = (const float*)d_in[1];  // [4096,4096]
    const float* W         = (const float*)d_in[2];  // [128,64]
    const float* att_self  = (const float*)d_in[3];  // [1,8,8]
    const float* att_neigh = (const float*)d_in[4];  // [1,8,8]
    const float* bias      = (const float*)d_in[5];  // [1,8,8]
    float* out             = (float*)d_out;          // [4096,64]

    feats_att_kernel<<<NN / 16, 256>>>(X, W, att_self, att_neigh);
    gat_row_kernel<<<NN / 4, 256>>>(A, bias, out);
}